// round 1
// baseline (speedup 1.0000x reference)
#include <cuda_runtime.h>
#include <math.h>

#define BB 64
#define SS 512
#define HH 1024
#define TT 24
#define NROWS (BB*SS)

// ---------------- device scratch (no allocations allowed) ----------------
__device__ float g_lse[NROWS];     // logsumexp_t emission[row,:]
__device__ float g_sc[NROWS];      // emission[row, target[row]]
__device__ int   g_mask[NROWS];    // decoded mask
__device__ float g_batch[BB];      // per-batch (score - logZ)
__device__ int   g_trans_nonzero;  // 1 if transition has any nonzero

__device__ __forceinline__ float neg_inf() { return __int_as_float(0xff800000); }

// ---------------- mask decode (dtype auto-detect) ----------------
__global__ void decode_mask_kernel(const void* __restrict__ mask_raw) {
    unsigned u0 = *(const unsigned*)mask_raw;  // mask[0][0..] is always true
    int i = blockIdx.x * blockDim.x + threadIdx.x;
    if (i >= NROWS) return;
    int m;
    if (u0 == 0x01010101u)      m = ((const unsigned char*)mask_raw)[i] != 0; // bool bytes
    else if (u0 == 0x3F800000u) m = ((const float*)mask_raw)[i] != 0.0f;      // float
    else                        m = ((const int*)mask_raw)[i] != 0;           // int32
    g_mask[i] = m;
}

// ---------------- transition zero-check ----------------
__global__ void check_trans_kernel(const float* __restrict__ trans) {
    __shared__ int nz;
    if (threadIdx.x == 0) nz = 0;
    __syncthreads();
    int local = 0;
    for (int i = threadIdx.x; i < TT * TT; i += blockDim.x)
        if (trans[i] != 0.0f) local = 1;
    if (local) atomicOr(&nz, 1);
    __syncthreads();
    if (threadIdx.x == 0) g_trans_nonzero = nz;
}

// ---------------- emission GEMM + fused LSE/score epilogue ----------------
// grid: NROWS/32 blocks, 256 threads (8 warps), each warp computes 4 rows x 24 t.
// dyn smem: W as float4 [24][256] (98304B) + bias (pad to 128B) + s_red [8][24] float4
#define SMEM_BYTES (98304 + 128 + 8*24*16)

__global__ void __launch_bounds__(256, 1)
emis_kernel(const float* __restrict__ feats,
            const float* __restrict__ W,
            const float* __restrict__ bias,
            const int*   __restrict__ target,
            float*       __restrict__ emis) {
    extern __shared__ unsigned char smem_raw[];
    float4* sW   = (float4*)smem_raw;                       // [24*256]
    float*  sb   = (float*)(smem_raw + 98304);              // [24]
    float4* sred = (float4*)(smem_raw + 98304 + 128);       // [8][24]

    // stage W (row-major [T][H]) and bias
    const float4* Wg = (const float4*)W;
    for (int i = threadIdx.x; i < TT * HH / 4; i += 256) sW[i] = Wg[i];
    if (threadIdx.x < TT) sb[threadIdx.x] = bias[threadIdx.x];
    __syncthreads();

    const int warp = threadIdx.x >> 5;
    const int lane = threadIdx.x & 31;
    const long row0 = ((long)blockIdx.x * 8 + warp) * 4;
    const float4* f4 = (const float4*)feats;

    float acc[TT][4];
    #pragma unroll
    for (int t = 0; t < TT; t++)
        #pragma unroll
        for (int r = 0; r < 4; r++) acc[t][r] = 0.0f;

    #pragma unroll
    for (int it = 0; it < 8; it++) {
        const int k4 = it * 32 + lane;      // float4 index within the 256-wide row
        float4 f[4];
        #pragma unroll
        for (int r = 0; r < 4; r++) f[r] = f4[(row0 + r) * 256 + k4];
        #pragma unroll
        for (int t = 0; t < TT; t++) {
            float4 w = sW[t * 256 + k4];
            #pragma unroll
            for (int r = 0; r < 4; r++)
                acc[t][r] += w.x * f[r].x + w.y * f[r].y + w.z * f[r].z + w.w * f[r].w;
        }
    }

    // reduce each accumulator to lane 0
    #pragma unroll
    for (int t = 0; t < TT; t++) {
        #pragma unroll
        for (int r = 0; r < 4; r++) {
            float v = acc[t][r];
            v += __shfl_down_sync(0xffffffffu, v, 16);
            v += __shfl_down_sync(0xffffffffu, v, 8);
            v += __shfl_down_sync(0xffffffffu, v, 4);
            v += __shfl_down_sync(0xffffffffu, v, 2);
            v += __shfl_down_sync(0xffffffffu, v, 1);
            acc[t][r] = v;
        }
    }
    // lane 0 transposes through smem so lane l owns t=l
    if (lane == 0) {
        #pragma unroll
        for (int t = 0; t < TT; t++)
            sred[warp * TT + t] = make_float4(acc[t][0], acc[t][1], acc[t][2], acc[t][3]);
    }
    __syncwarp();
    float4 e4 = make_float4(0, 0, 0, 0);
    float  bval = 0.0f;
    if (lane < TT) { e4 = sred[warp * TT + lane]; bval = sb[lane]; }
    float er[4] = { e4.x + bval, e4.y + bval, e4.z + bval, e4.w + bval };

    #pragma unroll
    for (int r = 0; r < 4; r++) {
        const long row = row0 + r;
        float e = (lane < TT) ? er[r] : neg_inf();
        if (lane < TT) emis[row * TT + lane] = e;
        // logsumexp over t
        float m = e;
        m = fmaxf(m, __shfl_xor_sync(0xffffffffu, m, 16));
        m = fmaxf(m, __shfl_xor_sync(0xffffffffu, m, 8));
        m = fmaxf(m, __shfl_xor_sync(0xffffffffu, m, 4));
        m = fmaxf(m, __shfl_xor_sync(0xffffffffu, m, 2));
        m = fmaxf(m, __shfl_xor_sync(0xffffffffu, m, 1));
        float ex = (lane < TT) ? expf(e - m) : 0.0f;
        ex += __shfl_xor_sync(0xffffffffu, ex, 16);
        ex += __shfl_xor_sync(0xffffffffu, ex, 8);
        ex += __shfl_xor_sync(0xffffffffu, ex, 4);
        ex += __shfl_xor_sync(0xffffffffu, ex, 2);
        ex += __shfl_xor_sync(0xffffffffu, ex, 1);
        float lse = m + logf(ex);
        int tg = target[row];
        float sc = __shfl_sync(0xffffffffu, e, tg);
        if (lane == 0) { g_lse[row] = lse; g_sc[row] = sc; }
    }
}

// ---------------- fast path (transition == 0): per-batch reduction ----------------
__global__ void batch_fast_kernel() {
    if (g_trans_nonzero) return;
    __shared__ float sh[256];
    const int b = blockIdx.x;
    float sum = 0.0f;
    for (int s = threadIdx.x; s < SS; s += 256) {
        const int idx = b * SS + s;
        const int m = g_mask[idx];
        float c = 0.0f;
        if (m) c += g_sc[idx];
        if (m || s == 0) c -= g_lse[idx];  // p0 = emission[:,0] unconditionally
        sum += c;
    }
    sh[threadIdx.x] = sum;
    __syncthreads();
    for (int off = 128; off > 0; off >>= 1) {
        if (threadIdx.x < off) sh[threadIdx.x] += sh[threadIdx.x + off];
        __syncthreads();
    }
    if (threadIdx.x == 0) g_batch[b] = sh[0];
}

// ---------------- generic path (transition != 0): warp-per-batch scan ----------------
__global__ void batch_generic_kernel(const float* __restrict__ trans,
                                     const int*   __restrict__ target,
                                     const float* __restrict__ emis) {
    if (!g_trans_nonzero) return;
    __shared__ float st[TT * TT];
    __shared__ float sp[TT];
    const int b = blockIdx.x;
    const int lane = threadIdx.x;
    for (int i = lane; i < TT * TT; i += 32) st[i] = trans[i];
    __syncwarp();

    // total score with transition terms
    float sum = 0.0f;
    for (int s = lane; s < SS; s += 32) {
        const long idx = (long)b * SS + s;
        if (g_mask[idx]) {
            float v = emis[idx * TT + target[idx]];
            if (s > 0) v += st[target[idx - 1] * TT + target[idx]];
            sum += v;
        }
    }
    sum += __shfl_xor_sync(0xffffffffu, sum, 16);
    sum += __shfl_xor_sync(0xffffffffu, sum, 8);
    sum += __shfl_xor_sync(0xffffffffu, sum, 4);
    sum += __shfl_xor_sync(0xffffffffu, sum, 2);
    sum += __shfl_xor_sync(0xffffffffu, sum, 1);

    if (lane < TT) sp[lane] = emis[(long)b * SS * TT + lane];
    __syncwarp();

    for (int s = 1; s < SS; s++) {
        if (g_mask[b * SS + s]) {
            float nv = 0.0f;
            if (lane < TT) {
                float m = neg_inf();
                #pragma unroll
                for (int j = 0; j < TT; j++) m = fmaxf(m, sp[j] + st[j * TT + lane]);
                float acc = 0.0f;
                #pragma unroll
                for (int j = 0; j < TT; j++) acc += expf(sp[j] + st[j * TT + lane] - m);
                nv = emis[((long)b * SS + s) * TT + lane] + m + logf(acc);
            }
            __syncwarp();
            if (lane < TT) sp[lane] = nv;
            __syncwarp();
        }
    }

    float e = (lane < TT) ? sp[lane] : neg_inf();
    float m = e;
    m = fmaxf(m, __shfl_xor_sync(0xffffffffu, m, 16));
    m = fmaxf(m, __shfl_xor_sync(0xffffffffu, m, 8));
    m = fmaxf(m, __shfl_xor_sync(0xffffffffu, m, 4));
    m = fmaxf(m, __shfl_xor_sync(0xffffffffu, m, 2));
    m = fmaxf(m, __shfl_xor_sync(0xffffffffu, m, 1));
    float ex = (lane < TT) ? expf(e - m) : 0.0f;
    ex += __shfl_xor_sync(0xffffffffu, ex, 16);
    ex += __shfl_xor_sync(0xffffffffu, ex, 8);
    ex += __shfl_xor_sync(0xffffffffu, ex, 4);
    ex += __shfl_xor_sync(0xffffffffu, ex, 2);
    ex += __shfl_xor_sync(0xffffffffu, ex, 1);
    float logZ = m + logf(ex);
    if (lane == 0) g_batch[b] = sum - logZ;
}

// ---------------- final loss ----------------
__global__ void loss_kernel(float* __restrict__ out, int has_loss) {
    __shared__ float sh[BB];
    sh[threadIdx.x] = g_batch[threadIdx.x];
    __syncthreads();
    if (threadIdx.x == 0) {
        float s = 0.0f;
        for (int i = 0; i < BB; i++) s += sh[i];
        if (has_loss) out[0] = -s / (float)BB;
    }
}

// ---------------- launch ----------------
extern "C" void kernel_launch(void* const* d_in, const int* in_sizes, int n_in,
                              void* d_out, int out_size) {
    const float* feats  = (const float*)d_in[0];   // (B,S,H)
    const int*   target = (const int*)d_in[1];     // (B,S)
    const void*  mask   = d_in[2];                 // (B,S) dtype auto-detected
    const float* W      = (const float*)d_in[3];   // (T,H)
    const float* bias   = (const float*)d_in[4];   // (T,)
    const float* trans  = (const float*)d_in[5];   // (T,T)

    float* out = (float*)d_out;
    const int has_loss = (out_size == NROWS * TT + 1) ? 1 : 0;
    float* emis = out + has_loss;                  // (loss, emission) flattened

    static int attr_set = 0;
    if (!attr_set) {
        cudaFuncSetAttribute(emis_kernel, cudaFuncAttributeMaxDynamicSharedMemorySize, SMEM_BYTES);
        attr_set = 1;
    }

    decode_mask_kernel<<<(NROWS + 255) / 256, 256>>>(mask);
    check_trans_kernel<<<1, 256>>>(trans);
    emis_kernel<<<NROWS / 32, 256, SMEM_BYTES>>>(feats, W, bias, target, emis);
    batch_fast_kernel<<<BB, 256>>>();
    batch_generic_kernel<<<BB, 32>>>(trans, target, emis);
    loss_kernel<<<1, BB>>>(out, has_loss);
}